// round 4
// baseline (speedup 1.0000x reference)
#include <cuda_runtime.h>
#include <cstdint>
#include <cstddef>

// Problem constants (fixed by the reference).
#define NN   100000
#define EE   1600000
#define DIN  64
#define DHID 64
#define DOUT 32
#define RR   8
#define NC1  (RR * DHID + DIN)    // 576: cols [0,512) = relation transforms, [512,576) = self-loop
#define NC2  (RR * DOUT + DOUT)   // 288: cols [0,256) = relation transforms, [256,288) = self-loop

// Scratch (allocation-free rule: __device__ globals).
__device__ float g_C1[(size_t)NN * NC1];   // feat @ Wcat1   [N, 576]  (~230 MB)
__device__ float g_h1[(size_t)NN * DHID];  // layer-1 pre-relu accumulator [N, 64]
__device__ float g_C2[(size_t)NN * NC2];   // relu(h1) @ Wcat2 [N, 288] (~115 MB)
__device__ float g_Wc1[DIN * NC1];         // packed [64, 576]
__device__ float g_Wc2[DHID * NC2];        // packed [64, 288]

// ---------------------------------------------------------------------------
// Pack W1[R,64,64] + Wself1[64,64] -> Wc1[64,576]; W2[R,64,32] + Wself2 -> Wc2[64,288]
// Wc[d, r*dout + o] = W[r, d, o]; Wc[d, R*dout + o] = Wself[d, o]
// ---------------------------------------------------------------------------
__global__ void pack_weights_k(const float* __restrict__ W1, const float* __restrict__ Ws1,
                               const float* __restrict__ W2, const float* __restrict__ Ws2)
{
    int t = blockIdx.x * blockDim.x + threadIdx.x;
    const int tot1 = DIN * NC1;
    const int tot2 = DHID * NC2;
    if (t < tot1) {
        int d = t / NC1, c = t - d * NC1;
        float v;
        if (c < RR * DHID) {
            int r = c / DHID, o = c - r * DHID;
            v = W1[((size_t)r * DIN + d) * DHID + o];
        } else {
            v = Ws1[(size_t)d * DHID + (c - RR * DHID)];
        }
        g_Wc1[t] = v;
    } else if (t < tot1 + tot2) {
        int u = t - tot1;
        int d = u / NC2, c = u - d * NC2;
        float v;
        if (c < RR * DOUT) {
            int r = c / DOUT, o = c - r * DOUT;
            v = W2[((size_t)r * DHID + d) * DOUT + o];
        } else {
            v = Ws2[(size_t)d * DOUT + (c - RR * DOUT)];
        }
        g_Wc2[u] = v;
    }
}

// ---------------------------------------------------------------------------
// SGEMM, K fixed at 64. C[M,Ncols] = op(A[M,64]) * B[64,Ncols], op = optional relu.
// BM=128, BN=64, 256 threads, thread tile 8x4.
// A staged k-major in smem (conflict-free STS: row index = lane within warp).
// ---------------------------------------------------------------------------
__global__ __launch_bounds__(256)
void sgemm_k64(const float* __restrict__ A, const float* __restrict__ B,
               float* __restrict__ C, int M, int Ncols, int reluA)
{
    __shared__ float As[64][128];   // [k][m], 32 KB
    __shared__ float Bs[64][64];    // [k][n], 16 KB
    const int t  = threadIdx.x;
    const int m0 = blockIdx.y * 128;
    const int n0 = blockIdx.x * 64;

    // Load A tile (128 rows x 64 cols), transpose into k-major smem.
    // idx -> (row = idx&127, c4 = (idx>>7)*4): STS bank = row%32 -> conflict-free.
#pragma unroll
    for (int i = 0; i < 8; i++) {
        int idx = t + i * 256;
        int row = idx & 127;
        int c4  = (idx >> 7) << 2;
        float4 v = make_float4(0.f, 0.f, 0.f, 0.f);
        int gm = m0 + row;
        if (gm < M) v = *reinterpret_cast<const float4*>(A + (size_t)gm * 64 + c4);
        if (reluA) {
            v.x = fmaxf(v.x, 0.f); v.y = fmaxf(v.y, 0.f);
            v.z = fmaxf(v.z, 0.f); v.w = fmaxf(v.w, 0.f);
        }
        As[c4 + 0][row] = v.x; As[c4 + 1][row] = v.y;
        As[c4 + 2][row] = v.z; As[c4 + 3][row] = v.w;
    }
    // Load B tile (64 x 64): already k-major in global, direct float4 copy.
#pragma unroll
    for (int i = 0; i < 4; i++) {
        int idx = t + i * 256;
        int row = idx >> 4;
        int c4  = (idx & 15) << 2;
        float4 v = make_float4(0.f, 0.f, 0.f, 0.f);
        int gn = n0 + c4;
        if (gn < Ncols) v = *reinterpret_cast<const float4*>(B + (size_t)row * Ncols + gn);
        *reinterpret_cast<float4*>(&Bs[row][c4]) = v;
    }
    __syncthreads();

    const int tx = t & 15;   // n direction: 4 cols each
    const int ty = t >> 4;   // m direction: 8 rows each
    float acc[8][4];
#pragma unroll
    for (int i = 0; i < 8; i++)
#pragma unroll
        for (int j = 0; j < 4; j++) acc[i][j] = 0.f;

#pragma unroll
    for (int k = 0; k < 64; k++) {
        float4 a0 = *reinterpret_cast<const float4*>(&As[k][ty * 8]);
        float4 a1 = *reinterpret_cast<const float4*>(&As[k][ty * 8 + 4]);
        float4 b  = *reinterpret_cast<const float4*>(&Bs[k][tx * 4]);
        float av[8] = {a0.x, a0.y, a0.z, a0.w, a1.x, a1.y, a1.z, a1.w};
        float bv[4] = {b.x, b.y, b.z, b.w};
#pragma unroll
        for (int i = 0; i < 8; i++)
#pragma unroll
            for (int j = 0; j < 4; j++)
                acc[i][j] = fmaf(av[i], bv[j], acc[i][j]);
    }

    const int gn = n0 + tx * 4;
    if (gn < Ncols) {
#pragma unroll
        for (int i = 0; i < 8; i++) {
            int gm = m0 + ty * 8 + i;
            if (gm < M)
                *reinterpret_cast<float4*>(C + (size_t)gm * Ncols + gn) =
                    make_float4(acc[i][0], acc[i][1], acc[i][2], acc[i][3]);
        }
    }
}

// ---------------------------------------------------------------------------
// Accumulator inits: self-loop + bias.
// ---------------------------------------------------------------------------
__global__ void init_h1_k(const float* __restrict__ b1, int Nn)
{
    int t = blockIdx.x * blockDim.x + threadIdx.x;
    if (t < Nn * DHID) {
        int n = t >> 6, o = t & 63;
        g_h1[t] = g_C1[(size_t)n * NC1 + RR * DHID + o] + __ldg(b1 + o);
    }
}

__global__ void init_out_k(const float* __restrict__ b2, float* __restrict__ out, int Nn)
{
    int t = blockIdx.x * blockDim.x + threadIdx.x;
    if (t < Nn * DOUT) {
        int n = t >> 5, o = t & 31;
        out[t] = g_C2[(size_t)n * NC2 + RR * DOUT + o] + __ldg(b2 + o);
    }
}

// ---------------------------------------------------------------------------
// Edge scatter: vectorized global reductions (red.global.add.v4.f32, sm_90+).
// ---------------------------------------------------------------------------
__device__ __forceinline__ void red_add_v4(float* p, float4 v)
{
    asm volatile("red.global.add.v4.f32 [%0], {%1,%2,%3,%4};"
                 :: "l"(__cvta_generic_to_global(p)),
                    "f"(v.x), "f"(v.y), "f"(v.z), "f"(v.w)
                 : "memory");
}

// Layer 1: 16 lanes per edge, 64 floats. Gather 256 B contiguous from g_C1.
__global__ void edge1_k(const int* __restrict__ src, const int* __restrict__ dst,
                        const int* __restrict__ ety, int Ne)
{
    int gid = blockIdx.x * blockDim.x + threadIdx.x;
    int e = gid >> 4;
    if (e >= Ne) return;
    int lane = gid & 15;
    int s = __ldg(src + e);
    int d = __ldg(dst + e);
    int r = __ldg(ety + e);
    float4 v = *reinterpret_cast<const float4*>(g_C1 + (size_t)s * NC1 + r * DHID + lane * 4);
    red_add_v4(g_h1 + (size_t)d * DHID + lane * 4, v);
}

// Layer 2: 8 lanes per edge, 32 floats. Gather 128 B contiguous from g_C2.
__global__ void edge2_k(const int* __restrict__ src, const int* __restrict__ dst,
                        const int* __restrict__ ety, float* __restrict__ out, int Ne)
{
    int gid = blockIdx.x * blockDim.x + threadIdx.x;
    int e = gid >> 3;
    if (e >= Ne) return;
    int lane = gid & 7;
    int s = __ldg(src + e);
    int d = __ldg(dst + e);
    int r = __ldg(ety + e);
    float4 v = *reinterpret_cast<const float4*>(g_C2 + (size_t)s * NC2 + r * DOUT + lane * 4);
    red_add_v4(out + (size_t)d * DOUT + lane * 4, v);
}

// ---------------------------------------------------------------------------
// kernel_launch: pack -> GEMM1 -> init1 -> scatter1 -> GEMM2(relu) -> init2 -> scatter2
// ---------------------------------------------------------------------------
extern "C" void kernel_launch(void* const* d_in, const int* in_sizes, int n_in,
                              void* d_out, int out_size)
{
    const float* feat = (const float*)d_in[0];
    const int*   src  = (const int*)  d_in[1];
    const int*   dst  = (const int*)  d_in[2];
    const int*   ety  = (const int*)  d_in[3];
    const float* W1   = (const float*)d_in[4];
    const float* Ws1  = (const float*)d_in[5];
    const float* b1   = (const float*)d_in[6];
    const float* W2   = (const float*)d_in[7];
    const float* Ws2  = (const float*)d_in[8];
    const float* b2   = (const float*)d_in[9];
    float* out = (float*)d_out;

    int Nn = in_sizes[0] / DIN;
    int Ne = in_sizes[1];

    // Symbol addresses for the generic GEMM kernel (host API, not a stream op:
    // executes at capture time, fine under graph capture; no allocation).
    float *pC1, *pC2, *pH1, *pWc1, *pWc2;
    cudaGetSymbolAddress((void**)&pC1,  g_C1);
    cudaGetSymbolAddress((void**)&pC2,  g_C2);
    cudaGetSymbolAddress((void**)&pH1,  g_h1);
    cudaGetSymbolAddress((void**)&pWc1, g_Wc1);
    cudaGetSymbolAddress((void**)&pWc2, g_Wc2);

    const int packTot = DIN * NC1 + DHID * NC2;
    pack_weights_k<<<(packTot + 255) / 256, 256>>>(W1, Ws1, W2, Ws2);

    dim3 g1(NC1 / 64, (Nn + 127) / 128);          // 9 x 782
    sgemm_k64<<<g1, 256>>>(feat, pWc1, pC1, Nn, NC1, 0);

    init_h1_k<<<(Nn * DHID + 255) / 256, 256>>>(b1, Nn);
    edge1_k<<<((size_t)Ne * 16 + 255) / 256, 256>>>(src, dst, ety, Ne);

    dim3 g2((NC2 + 63) / 64, (Nn + 127) / 128);   // 5 x 782
    sgemm_k64<<<g2, 256>>>(pH1, pWc2, pC2, Nn, NC2, 1);

    init_out_k<<<(Nn * DOUT + 255) / 256, 256>>>(b2, out, Nn);
    edge2_k<<<((size_t)Ne * 8 + 255) / 256, 256>>>(src, dst, ety, out, Ne);
}

// round 8
// speedup vs baseline: 1.2184x; 1.2184x over previous
#include <cuda_runtime.h>
#include <cuda_bf16.h>
#include <cstdint>
#include <cstddef>

// Problem constants (fixed by the reference).
#define NN    100000
#define EE    1600000
#define DIN   64
#define DHID  64
#define DOUT  32
#define RR    8
#define NC1   (RR * DHID + DIN)   // 576 = 9 * 64
#define NC2P  320                 // 288 real cols (256 rel + 32 self) padded to 5*64
#define MT64  1563                // ceil(100000/64)
#define MPAD64 (MT64 * 64)        // 100032

// GEMM tile geometry: BM=64, BN=64. A row = [Ah(64)|Al(64)|pad(8)] = 136 bf16.
// B row = [Bh(64)|Bl(64)|pad(8)] = 136 bf16. 272 B/row; 272 % 128 == 16 ->
// ldmatrix phases conflict-free. Error-compensated product:
//   C = Ah*Bh + Al*Bh + Ah*Bl   (combos (Aoff,Boff) = (0,0),(64,0),(0,64))
#define KSTRIDE 136
#define TILE_E  (64 * KSTRIDE)    // 8704 bf16 = 17408 B per tile (A or B)
#define SMEM_BYTES (2 * TILE_E * 2)  // 34816 B  (<= 48 KB: no opt-in needed)

// ---------------------------------------------------------------------------
// Scratch (__device__ globals; allocation-free rule).
// ---------------------------------------------------------------------------
__device__ float         g_C1[(size_t)NN * NC1];        // feat @ Wcat1 [N,576]  (~230 MB)
__device__ float         g_h1[(size_t)NN * DHID];       // layer-1 accumulator [N,64]
__device__ float         g_C2[(size_t)NN * NC2P];       // relu(h1) @ Wcat2 [N,320] (~128 MB)
__device__ __nv_bfloat16 g_As[(size_t)MT64 * TILE_E];   // split A tiles (~27 MB)
__device__ __nv_bfloat16 g_B1s[9 * TILE_E];             // layer-1 B tiles
__device__ __nv_bfloat16 g_B2s[5 * TILE_E];             // layer-2 B tiles

// ---------------------------------------------------------------------------
// PTX helpers (base sm_103-safe: ldmatrix + mma.sync only).
// ---------------------------------------------------------------------------
__device__ __forceinline__ uint32_t smem_u32(const void* p) {
    uint32_t a;
    asm("{ .reg .u64 t; cvta.to.shared.u64 t, %1; cvt.u32.u64 %0, t; }" : "=r"(a) : "l"(p));
    return a;
}

#define LDSM4(r0, r1, r2, r3, addr)                                             \
    asm volatile("ldmatrix.sync.aligned.m8n8.x4.shared.b16 {%0,%1,%2,%3}, [%4];" \
                 : "=r"(r0), "=r"(r1), "=r"(r2), "=r"(r3) : "r"(addr))

#define MMA16816(c0, c1, c2, c3, a0, a1, a2, a3, b0, b1)                        \
    asm volatile("mma.sync.aligned.m16n8k16.row.col.f32.bf16.bf16.f32 "          \
                 "{%0,%1,%2,%3},{%4,%5,%6,%7},{%8,%9},{%0,%1,%2,%3};"            \
                 : "+f"(c0), "+f"(c1), "+f"(c2), "+f"(c3)                        \
                 : "r"(a0), "r"(a1), "r"(a2), "r"(a3), "r"(b0), "r"(b1))

// ---------------------------------------------------------------------------
// Split fp32 [M,64] -> A tiles [tile][64][136] bf16: [0:64)=Ah, [64:128)=Al,
// [128:136)=0. Optional relu applied before split.
// ---------------------------------------------------------------------------
__global__ void split_A_k(const float* __restrict__ X, int Nn, int doRelu)
{
    int t = blockIdx.x * blockDim.x + threadIdx.x;   // MPAD64*32 threads
    if (t >= MPAD64 * 32) return;
    int mg = t >> 5;
    int j  = t & 31;
    int kp = j << 1;                                  // even k in [0,64)
    int tile = mg >> 6, m = mg & 63;
    float a0 = 0.f, a1 = 0.f;
    if (mg < Nn) {
        a0 = X[(size_t)mg * 64 + kp];
        a1 = X[(size_t)mg * 64 + kp + 1];
        if (doRelu) { a0 = fmaxf(a0, 0.f); a1 = fmaxf(a1, 0.f); }
    }
    __nv_bfloat16 h0 = __float2bfloat16(a0);
    __nv_bfloat16 h1 = __float2bfloat16(a1);
    __nv_bfloat16 l0 = __float2bfloat16(a0 - __bfloat162float(h0));
    __nv_bfloat16 l1 = __float2bfloat16(a1 - __bfloat162float(h1));
    __nv_bfloat162 hv; hv.x = h0; hv.y = h1;
    __nv_bfloat162 lv; lv.x = l0; lv.y = l1;
    __nv_bfloat16* row = g_As + (size_t)tile * TILE_E + m * KSTRIDE;
    *reinterpret_cast<__nv_bfloat162*>(row + kp)      = hv;
    *reinterpret_cast<__nv_bfloat162*>(row + 64 + kp) = lv;
    if (j == 0) {
        __nv_bfloat162 z; z.x = __float2bfloat16(0.f); z.y = z.x;
#pragma unroll
        for (int q = 0; q < 4; q++)
            *reinterpret_cast<__nv_bfloat162*>(row + 128 + 2 * q) = z;
    }
}

// ---------------------------------------------------------------------------
// Pack weights -> B tiles [tile][64][136] bf16: rows are output columns n,
// cols: [0:64)=Bh, [64:128)=Bl, [128:136)=0.
// ---------------------------------------------------------------------------
__global__ void pack_B_k(const float* __restrict__ W1, const float* __restrict__ Ws1,
                         const float* __restrict__ W2, const float* __restrict__ Ws2)
{
    int u = blockIdx.x * blockDim.x + threadIdx.x;    // 14 * 4096 threads
    if (u >= 14 * 4096) return;
    int t14 = u >> 12;
    int v   = u & 4095;
    int n   = v >> 6;
    int kk  = v & 63;
    __nv_bfloat16* base;
    int tile;
    float w = 0.f;
    if (t14 < 9) {
        tile = t14; base = g_B1s;
        int col = tile * 64 + n;
        if (col < 512) { int r = col >> 6, o = col & 63; w = W1[((size_t)r * 64 + kk) * 64 + o]; }
        else           { w = Ws1[(size_t)kk * 64 + (col - 512)]; }
    } else {
        tile = t14 - 9; base = g_B2s;
        int col = tile * 64 + n;
        if (col < 256)      { int r = col >> 5, o = col & 31; w = W2[((size_t)r * 64 + kk) * 32 + o]; }
        else if (col < 288) { w = Ws2[(size_t)kk * 32 + (col - 256)]; }
    }
    __nv_bfloat16 h = __float2bfloat16(w);
    __nv_bfloat16 l = __float2bfloat16(w - __bfloat162float(h));
    __nv_bfloat16* row = base + (size_t)tile * TILE_E + n * KSTRIDE;
    row[kk]      = h;
    row[64 + kk] = l;
    if (kk < 8) row[128 + kk] = __float2bfloat16(0.f);
}

// ---------------------------------------------------------------------------
// HMMA GEMM: C[M, ncols] = compensated A*B^T, fp32 accumulate.
// CTA: 256 threads, M-tile 64, loops over ntiles N-tiles of 64.
// Warps 4(m) x 2(n); each warp m16 x n32 = 4 n8 tiles; 12 k16 steps
// (3 combos x 4 k-chunks).
// ---------------------------------------------------------------------------
__global__ void __launch_bounds__(256)
gemm_mma(const __nv_bfloat16* __restrict__ gA, const __nv_bfloat16* __restrict__ gB,
         float* __restrict__ C, int Nn, int ntiles, int ncols)
{
    extern __shared__ __nv_bfloat16 sm[];             // A: [0, TILE_E), B: [TILE_E, +TILE_E)
    const int tid  = threadIdx.x;
    const int lane = tid & 31;
    const int wid  = tid >> 5;
    const int wm   = wid & 3;                          // m: 4 warps * 16 rows
    const int wn   = wid >> 2;                         // n: 2 warps * 32 cols
    const int m0   = blockIdx.x * 64;

    // Copy A tile (17408 B, linear).
    {
        const float4* src = reinterpret_cast<const float4*>(gA + (size_t)blockIdx.x * TILE_E);
        float4* dst = reinterpret_cast<float4*>(sm);
        for (int i = tid; i < TILE_E / 8; i += 256) dst[i] = src[i];
    }

    const uint32_t smA = smem_u32(sm);
    const uint32_t smB = smA + TILE_E * 2;

    // ldmatrix lane base addresses (combo/k offset added in loop).
    // A x4: rows wm*16 + (lane&15), k-half by lane>>4 -> a0..a3 in mma order.
    const uint32_t aAddr  = smA + (uint32_t)(wm * 16 + (lane & 15)) * (KSTRIDE * 2)
                          + (uint32_t)((lane >> 4) << 4);
    // B x4: lanes 0-7 rows n0-7 k0, 8-15 rows n0-7 k16B, 16-23 n8-15 k0, 24-31 n8-15 k16B.
    const uint32_t bAddr0 = smB + (uint32_t)(wn * 32 + ((lane >> 4) << 3) + (lane & 7)) * (KSTRIDE * 2)
                          + (uint32_t)(((lane >> 3) & 1) << 4);
    const uint32_t bAddr1 = bAddr0 + 16 * (KSTRIDE * 2);

    for (int nt = 0; nt < ntiles; nt++) {
        __syncthreads();  // A copy visible (first iter); B reads done (later iters)
        {
            const float4* src = reinterpret_cast<const float4*>(gB + (size_t)nt * TILE_E);
            float4* dst = reinterpret_cast<float4*>(sm + TILE_E);
            for (int i = tid; i < TILE_E / 8; i += 256) dst[i] = src[i];
        }
        __syncthreads();

        float c[4][4];
#pragma unroll
        for (int i = 0; i < 4; i++)
#pragma unroll
            for (int j = 0; j < 4; j++) c[i][j] = 0.f;

#pragma unroll
        for (int s = 0; s < 12; s++) {
            const int combo = s >> 2;                  // 0:(Ah,Bh) 1:(Al,Bh) 2:(Ah,Bl)
            const int ks    = s & 3;
            const uint32_t ao = (combo == 1 ? 128u : 0u) + (uint32_t)ks * 32u;
            const uint32_t bo = (combo == 2 ? 128u : 0u) + (uint32_t)ks * 32u;
            uint32_t a[4], b0[4], b1[4];
            LDSM4(a[0], a[1], a[2], a[3], aAddr + ao);
            LDSM4(b0[0], b0[1], b0[2], b0[3], bAddr0 + bo);
            LDSM4(b1[0], b1[1], b1[2], b1[3], bAddr1 + bo);
            MMA16816(c[0][0], c[0][1], c[0][2], c[0][3], a[0], a[1], a[2], a[3], b0[0], b0[1]);
            MMA16816(c[1][0], c[1][1], c[1][2], c[1][3], a[0], a[1], a[2], a[3], b0[2], b0[3]);
            MMA16816(c[2][0], c[2][1], c[2][2], c[2][3], a[0], a[1], a[2], a[3], b1[0], b1[1]);
            MMA16816(c[3][0], c[3][1], c[3][2], c[3][3], a[0], a[1], a[2], a[3], b1[2], b1[3]);
        }

        // Epilogue: direct fragment stores (float2 per row-half).
        const int colBase = nt * 64 + wn * 32 + 2 * (lane & 3);
        const int row0 = m0 + wm * 16 + (lane >> 2);
#pragma unroll
        for (int j = 0; j < 4; j++) {
            int col = colBase + j * 8;
            if (row0 < Nn)
                *reinterpret_cast<float2*>(C + (size_t)row0 * ncols + col) =
                    make_float2(c[j][0], c[j][1]);
            if (row0 + 8 < Nn)
                *reinterpret_cast<float2*>(C + (size_t)(row0 + 8) * ncols + col) =
                    make_float2(c[j][2], c[j][3]);
        }
    }
}

// ---------------------------------------------------------------------------
// Accumulator inits: self-loop + bias.
// ---------------------------------------------------------------------------
__global__ void init_h1_k(const float* __restrict__ b1, int Nn)
{
    int t = blockIdx.x * blockDim.x + threadIdx.x;
    if (t < Nn * DHID) {
        int n = t >> 6, o = t & 63;
        g_h1[t] = g_C1[(size_t)n * NC1 + RR * DHID + o] + __ldg(b1 + o);
    }
}

__global__ void init_out_k(const float* __restrict__ b2, float* __restrict__ out, int Nn)
{
    int t = blockIdx.x * blockDim.x + threadIdx.x;
    if (t < Nn * DOUT) {
        int n = t >> 5, o = t & 31;
        out[t] = g_C2[(size_t)n * NC2P + RR * DOUT + o] + __ldg(b2 + o);
    }
}

// ---------------------------------------------------------------------------
// Edge scatter: vectorized global reductions (red.global.add.v4.f32).
// ---------------------------------------------------------------------------
__device__ __forceinline__ void red_add_v4(float* p, float4 v)
{
    asm volatile("red.global.add.v4.f32 [%0], {%1,%2,%3,%4};"
                 :: "l"(__cvta_generic_to_global(p)),
                    "f"(v.x), "f"(v.y), "f"(v.z), "f"(v.w)
                 : "memory");
}

__global__ void edge1_k(const int* __restrict__ src, const int* __restrict__ dst,
                        const int* __restrict__ ety, int Ne)
{
    int gid = blockIdx.x * blockDim.x + threadIdx.x;
    int e = gid >> 4;
    if (e >= Ne) return;
    int lane = gid & 15;
    int s = __ldg(src + e), d = __ldg(dst + e), r = __ldg(ety + e);
    float4 v = *reinterpret_cast<const float4*>(g_C1 + (size_t)s * NC1 + r * DHID + lane * 4);
    red_add_v4(g_h1 + (size_t)d * DHID + lane * 4, v);
}

__global__ void edge2_k(const int* __restrict__ src, const int* __restrict__ dst,
                        const int* __restrict__ ety, float* __restrict__ out, int Ne)
{
    int gid = blockIdx.x * blockDim.x + threadIdx.x;
    int e = gid >> 3;
    if (e >= Ne) return;
    int lane = gid & 7;
    int s = __ldg(src + e), d = __ldg(dst + e), r = __ldg(ety + e);
    float4 v = *reinterpret_cast<const float4*>(g_C2 + (size_t)s * NC2P + r * DOUT + lane * 4);
    red_add_v4(out + (size_t)d * DOUT + lane * 4, v);
}

// ---------------------------------------------------------------------------
// kernel_launch
// ---------------------------------------------------------------------------
extern "C" void kernel_launch(void* const* d_in, const int* in_sizes, int n_in,
                              void* d_out, int out_size)
{
    const float* feat = (const float*)d_in[0];
    const int*   src  = (const int*)  d_in[1];
    const int*   dst  = (const int*)  d_in[2];
    const int*   ety  = (const int*)  d_in[3];
    const float* W1   = (const float*)d_in[4];
    const float* Ws1  = (const float*)d_in[5];
    const float* b1   = (const float*)d_in[6];
    const float* W2   = (const float*)d_in[7];
    const float* Ws2  = (const float*)d_in[8];
    const float* b2   = (const float*)d_in[9];
    float* out = (float*)d_out;

    int Nn = in_sizes[0] / DIN;
    int Ne = in_sizes[1];
    int MT = (Nn + 63) / 64;

    float *pC1, *pC2, *pH1;
    __nv_bfloat16 *pAs, *pB1, *pB2;
    cudaGetSymbolAddress((void**)&pC1, g_C1);
    cudaGetSymbolAddress((void**)&pC2, g_C2);
    cudaGetSymbolAddress((void**)&pH1, g_h1);
    cudaGetSymbolAddress((void**)&pAs, g_As);
    cudaGetSymbolAddress((void**)&pB1, g_B1s);
    cudaGetSymbolAddress((void**)&pB2, g_B2s);

    pack_B_k<<<(14 * 4096 + 255) / 256, 256>>>(W1, Ws1, W2, Ws2);
    split_A_k<<<(MPAD64 * 32 + 255) / 256, 256>>>(feat, Nn, 0);

    gemm_mma<<<MT, 256, SMEM_BYTES>>>(pAs, pB1, pC1, Nn, 9, NC1);

    init_h1_k<<<(Nn * DHID + 255) / 256, 256>>>(b1, Nn);
    edge1_k<<<(int)(((size_t)Ne * 16 + 255) / 256), 256>>>(src, dst, ety, Ne);

    split_A_k<<<(MPAD64 * 32 + 255) / 256, 256>>>(pH1, Nn, 1);
    gemm_mma<<<MT, 256, SMEM_BYTES>>>(pAs, pB2, pC2, Nn, 5, NC2P);

    init_out_k<<<(Nn * DOUT + 255) / 256, 256>>>(b2, out, Nn);
    edge2_k<<<(int)(((size_t)Ne * 8 + 255) / 256), 256>>>(src, dst, ety, out, Ne);
}

// round 11
// speedup vs baseline: 1.2952x; 1.0630x over previous
#include <cuda_runtime.h>
#include <cuda_bf16.h>
#include <cstdint>
#include <cstddef>

// Problem constants (fixed by the reference).
#define NN    100000
#define EE    1600000
#define DIN   64
#define DHID  64
#define DOUT  32
#define RR    8
#define NC1   (RR * DHID + DIN)   // 576 = 9 * 64
#define NC2P  320                 // 288 real cols (256 rel + 32 self) padded to 5*64
#define MT64  1563                // ceil(100000/64)
#define MPAD64 (MT64 * 64)        // 100032

// GEMM tile geometry: BM=64, BN=64. A row = [Ah(64)|Al(64)|pad(8)] = 136 bf16.
// 272 B/row; 272 % 128 == 16 -> ldmatrix phases conflict-free.
// Error-compensated product: C = Ah*Bh + Al*Bh + Ah*Bl.
#define KSTRIDE 136
#define TILE_E  (64 * KSTRIDE)    // 8704 bf16 = 17408 B per tile
#define SMEM_BYTES (2 * TILE_E * 2)  // 34816 B (<= 48 KB, no opt-in)

// CSR scan geometry.
#define SCAN_N  (NN + 1)          // 100001
#define SCAN_B  1024
#define SCAN_NB ((SCAN_N + SCAN_B - 1) / SCAN_B)  // 98

// ---------------------------------------------------------------------------
// Scratch (__device__ globals; allocation-free rule).
// ---------------------------------------------------------------------------
__device__ float         g_C1[(size_t)NN * NC1];        // feat @ Wcat1 [N,576]
__device__ float         g_h1[(size_t)NN * DHID];       // layer-1 activations [N,64]
__device__ float         g_C2[(size_t)NN * NC2P];       // relu(h1) @ Wcat2 [N,320]
__device__ __nv_bfloat16 g_As[(size_t)MT64 * TILE_E];   // split A tiles
__device__ __nv_bfloat16 g_B1s[9 * TILE_E];             // layer-1 B tiles
__device__ __nv_bfloat16 g_B2s[5 * TILE_E];             // layer-2 B tiles
__device__ int           g_cnt[SCAN_N];                 // CSR offsets (post-scan)
__device__ int           g_pos[NN];                     // scatter cursors
__device__ int           g_bsum[SCAN_NB];               // scan partials
__device__ int           g_eidx[EE];                    // packed src | (ety<<20)

// ---------------------------------------------------------------------------
// PTX helpers (base sm_103-safe: ldmatrix + mma.sync only).
// ---------------------------------------------------------------------------
__device__ __forceinline__ uint32_t smem_u32(const void* p) {
    uint32_t a;
    asm("{ .reg .u64 t; cvta.to.shared.u64 t, %1; cvt.u32.u64 %0, t; }" : "=r"(a) : "l"(p));
    return a;
}

#define LDSM4(r0, r1, r2, r3, addr)                                             \
    asm volatile("ldmatrix.sync.aligned.m8n8.x4.shared.b16 {%0,%1,%2,%3}, [%4];" \
                 : "=r"(r0), "=r"(r1), "=r"(r2), "=r"(r3) : "r"(addr))

#define MMA16816(c0, c1, c2, c3, a0, a1, a2, a3, b0, b1)                        \
    asm volatile("mma.sync.aligned.m16n8k16.row.col.f32.bf16.bf16.f32 "          \
                 "{%0,%1,%2,%3},{%4,%5,%6,%7},{%8,%9},{%0,%1,%2,%3};"            \
                 : "+f"(c0), "+f"(c1), "+f"(c2), "+f"(c3)                        \
                 : "r"(a0), "r"(a1), "r"(a2), "r"(a3), "r"(b0), "r"(b1))

// ---------------------------------------------------------------------------
// Split fp32 [M,64] -> A tiles [tile][64][136] bf16: [0:64)=Ah, [64:128)=Al.
// ---------------------------------------------------------------------------
__global__ void split_A_k(const float* __restrict__ X, int Nn, int doRelu)
{
    int t = blockIdx.x * blockDim.x + threadIdx.x;
    if (t >= MPAD64 * 32) return;
    int mg = t >> 5;
    int j  = t & 31;
    int kp = j << 1;
    int tile = mg >> 6, m = mg & 63;
    float a0 = 0.f, a1 = 0.f;
    if (mg < Nn) {
        a0 = X[(size_t)mg * 64 + kp];
        a1 = X[(size_t)mg * 64 + kp + 1];
        if (doRelu) { a0 = fmaxf(a0, 0.f); a1 = fmaxf(a1, 0.f); }
    }
    __nv_bfloat16 h0 = __float2bfloat16(a0);
    __nv_bfloat16 h1 = __float2bfloat16(a1);
    __nv_bfloat16 l0 = __float2bfloat16(a0 - __bfloat162float(h0));
    __nv_bfloat16 l1 = __float2bfloat16(a1 - __bfloat162float(h1));
    __nv_bfloat162 hv; hv.x = h0; hv.y = h1;
    __nv_bfloat162 lv; lv.x = l0; lv.y = l1;
    __nv_bfloat16* row = g_As + (size_t)tile * TILE_E + m * KSTRIDE;
    *reinterpret_cast<__nv_bfloat162*>(row + kp)      = hv;
    *reinterpret_cast<__nv_bfloat162*>(row + 64 + kp) = lv;
    if (j == 0) {
        __nv_bfloat162 z; z.x = __float2bfloat16(0.f); z.y = z.x;
#pragma unroll
        for (int q = 0; q < 4; q++)
            *reinterpret_cast<__nv_bfloat162*>(row + 128 + 2 * q) = z;
    }
}

// ---------------------------------------------------------------------------
// Pack weights -> B tiles [tile][64][136] bf16: [0:64)=Bh, [64:128)=Bl.
// ---------------------------------------------------------------------------
__global__ void pack_B_k(const float* __restrict__ W1, const float* __restrict__ Ws1,
                         const float* __restrict__ W2, const float* __restrict__ Ws2)
{
    int u = blockIdx.x * blockDim.x + threadIdx.x;
    if (u >= 14 * 4096) return;
    int t14 = u >> 12;
    int v   = u & 4095;
    int n   = v >> 6;
    int kk  = v & 63;
    __nv_bfloat16* base;
    int tile;
    float w = 0.f;
    if (t14 < 9) {
        tile = t14; base = g_B1s;
        int col = tile * 64 + n;
        if (col < 512) { int r = col >> 6, o = col & 63; w = W1[((size_t)r * 64 + kk) * 64 + o]; }
        else           { w = Ws1[(size_t)kk * 64 + (col - 512)]; }
    } else {
        tile = t14 - 9; base = g_B2s;
        int col = tile * 64 + n;
        if (col < 256)      { int r = col >> 5, o = col & 31; w = W2[((size_t)r * 64 + kk) * 32 + o]; }
        else if (col < 288) { w = Ws2[(size_t)kk * 32 + (col - 256)]; }
    }
    __nv_bfloat16 h = __float2bfloat16(w);
    __nv_bfloat16 l = __float2bfloat16(w - __bfloat162float(h));
    __nv_bfloat16* row = base + (size_t)tile * TILE_E + n * KSTRIDE;
    row[kk]      = h;
    row[64 + kk] = l;
    if (kk < 8) row[128 + kk] = __float2bfloat16(0.f);
}

// ---------------------------------------------------------------------------
// HMMA GEMM (unchanged from the 442 us version).
// ---------------------------------------------------------------------------
__global__ void __launch_bounds__(256)
gemm_mma(const __nv_bfloat16* __restrict__ gA, const __nv_bfloat16* __restrict__ gB,
         float* __restrict__ C, int Nn, int ntiles, int ncols)
{
    extern __shared__ __nv_bfloat16 sm[];
    const int tid  = threadIdx.x;
    const int lane = tid & 31;
    const int wid  = tid >> 5;
    const int wm   = wid & 3;
    const int wn   = wid >> 2;
    const int m0   = blockIdx.x * 64;

    {
        const float4* src = reinterpret_cast<const float4*>(gA + (size_t)blockIdx.x * TILE_E);
        float4* dst = reinterpret_cast<float4*>(sm);
        for (int i = tid; i < TILE_E / 8; i += 256) dst[i] = src[i];
    }

    const uint32_t smA = smem_u32(sm);
    const uint32_t smB = smA + TILE_E * 2;

    const uint32_t aAddr  = smA + (uint32_t)(wm * 16 + (lane & 15)) * (KSTRIDE * 2)
                          + (uint32_t)((lane >> 4) << 4);
    const uint32_t bAddr0 = smB + (uint32_t)(wn * 32 + ((lane >> 4) << 3) + (lane & 7)) * (KSTRIDE * 2)
                          + (uint32_t)(((lane >> 3) & 1) << 4);
    const uint32_t bAddr1 = bAddr0 + 16 * (KSTRIDE * 2);

    for (int nt = 0; nt < ntiles; nt++) {
        __syncthreads();
        {
            const float4* src = reinterpret_cast<const float4*>(gB + (size_t)nt * TILE_E);
            float4* dst = reinterpret_cast<float4*>(sm + TILE_E);
            for (int i = tid; i < TILE_E / 8; i += 256) dst[i] = src[i];
        }
        __syncthreads();

        float c[4][4];
#pragma unroll
        for (int i = 0; i < 4; i++)
#pragma unroll
            for (int j = 0; j < 4; j++) c[i][j] = 0.f;

#pragma unroll
        for (int s = 0; s < 12; s++) {
            const int combo = s >> 2;
            const int ks    = s & 3;
            const uint32_t ao = (combo == 1 ? 128u : 0u) + (uint32_t)ks * 32u;
            const uint32_t bo = (combo == 2 ? 128u : 0u) + (uint32_t)ks * 32u;
            uint32_t a[4], b0[4], b1[4];
            LDSM4(a[0], a[1], a[2], a[3], aAddr + ao);
            LDSM4(b0[0], b0[1], b0[2], b0[3], bAddr0 + bo);
            LDSM4(b1[0], b1[1], b1[2], b1[3], bAddr1 + bo);
            MMA16816(c[0][0], c[0][1], c[0][2], c[0][3], a[0], a[1], a[2], a[3], b0[0], b0[1]);
            MMA16816(c[1][0], c[1][1], c[1][2], c[1][3], a[0], a[1], a[2], a[3], b0[2], b0[3]);
            MMA16816(c[2][0], c[2][1], c[2][2], c[2][3], a[0], a[1], a[2], a[3], b1[0], b1[1]);
            MMA16816(c[3][0], c[3][1], c[3][2], c[3][3], a[0], a[1], a[2], a[3], b1[2], b1[3]);
        }

        const int colBase = nt * 64 + wn * 32 + 2 * (lane & 3);
        const int row0 = m0 + wm * 16 + (lane >> 2);
#pragma unroll
        for (int j = 0; j < 4; j++) {
            int col = colBase + j * 8;
            if (row0 < Nn)
                *reinterpret_cast<float2*>(C + (size_t)row0 * ncols + col) =
                    make_float2(c[j][0], c[j][1]);
            if (row0 + 8 < Nn)
                *reinterpret_cast<float2*>(C + (size_t)(row0 + 8) * ncols + col) =
                    make_float2(c[j][2], c[j][3]);
        }
    }
}

// ---------------------------------------------------------------------------
// CSR build: zero -> histogram -> block scan (3 kernels) -> scatter.
// Counts stored shifted (+1): inclusive scan yields exclusive offsets.
// ---------------------------------------------------------------------------
__global__ void zero_cnt_k()
{
    int t = blockIdx.x * blockDim.x + threadIdx.x;
    if (t < SCAN_N) g_cnt[t] = 0;
}

__global__ void hist_k(const int* __restrict__ dst, int Ne)
{
    int e = blockIdx.x * blockDim.x + threadIdx.x;
    if (e < Ne) atomicAdd(&g_cnt[dst[e] + 1], 1);
}

__global__ void scan1_k()
{
    __shared__ int sh[SCAN_B];
    int i = blockIdx.x * SCAN_B + threadIdx.x;
    int v = (i < SCAN_N) ? g_cnt[i] : 0;
    sh[threadIdx.x] = v;
    __syncthreads();
#pragma unroll
    for (int off = 1; off < SCAN_B; off <<= 1) {
        int t = (threadIdx.x >= off) ? sh[threadIdx.x - off] : 0;
        __syncthreads();
        sh[threadIdx.x] += t;
        __syncthreads();
    }
    if (i < SCAN_N) g_cnt[i] = sh[threadIdx.x];
    if (threadIdx.x == SCAN_B - 1) g_bsum[blockIdx.x] = sh[SCAN_B - 1];
}

__global__ void scan2_k()
{
    __shared__ int sh[SCAN_NB];
    int t = threadIdx.x;
    if (t < SCAN_NB) sh[t] = g_bsum[t];
    __syncthreads();
    if (t == 0) {
        int run = 0;
        for (int i = 0; i < SCAN_NB; i++) { int c = sh[i]; sh[i] = run; run += c; }
    }
    __syncthreads();
    if (t < SCAN_NB) g_bsum[t] = sh[t];
}

__global__ void scan3_k()
{
    int i = blockIdx.x * blockDim.x + threadIdx.x;
    if (i < SCAN_N) {
        int v = g_cnt[i] + g_bsum[i / SCAN_B];
        g_cnt[i] = v;
        if (i < NN) g_pos[i] = v;
    }
}

__global__ void scatter_k(const int* __restrict__ src, const int* __restrict__ dst,
                          const int* __restrict__ ety, int Ne)
{
    int e = blockIdx.x * blockDim.x + threadIdx.x;
    if (e >= Ne) return;
    int p = atomicAdd(&g_pos[dst[e]], 1);
    g_eidx[p] = src[e] | (ety[e] << 20);
}

// ---------------------------------------------------------------------------
// Gather-side reductions (replace edge scatter + init kernels).
// Layer 1: 16 lanes per dst node, register accumulation, self+bias fused.
// ---------------------------------------------------------------------------
__global__ void __launch_bounds__(256)
gather1_k(const float* __restrict__ b1, int Nn)
{
    int gid = blockIdx.x * blockDim.x + threadIdx.x;
    int n = gid >> 4;
    if (n >= Nn) return;
    int l = gid & 15;

    const float4 bb = *reinterpret_cast<const float4*>(b1 + l * 4);
    float4 acc = *reinterpret_cast<const float4*>(g_C1 + (size_t)n * NC1 + RR * DHID + l * 4);
    acc.x += bb.x; acc.y += bb.y; acc.z += bb.z; acc.w += bb.w;

    const int beg = g_cnt[n], end = g_cnt[n + 1];
    for (int base = beg; base < end; base += 16) {
        int myIdx = (base + l < end) ? __ldg(g_eidx + base + l) : 0;
        int cnt = end - base; if (cnt > 16) cnt = 16;
        for (int j = 0; j < cnt; j++) {
            int pk = __shfl_sync(0xFFFFFFFFu, myIdx, j, 16);
            int s = pk & 0xFFFFF;
            int r = pk >> 20;
            float4 v = *reinterpret_cast<const float4*>(
                g_C1 + (size_t)s * NC1 + r * DHID + l * 4);
            acc.x += v.x; acc.y += v.y; acc.z += v.z; acc.w += v.w;
        }
    }
    *reinterpret_cast<float4*>(g_h1 + (size_t)n * DHID + l * 4) = acc;
}

// Layer 2: 8 lanes per dst node.
__global__ void __launch_bounds__(256)
gather2_k(const float* __restrict__ b2, float* __restrict__ out, int Nn)
{
    int gid = blockIdx.x * blockDim.x + threadIdx.x;
    int n = gid >> 3;
    if (n >= Nn) return;
    int l = gid & 7;

    const float4 bb = *reinterpret_cast<const float4*>(b2 + l * 4);
    float4 acc = *reinterpret_cast<const float4*>(g_C2 + (size_t)n * NC2P + RR * DOUT + l * 4);
    acc.x += bb.x; acc.y += bb.y; acc.z += bb.z; acc.w += bb.w;

    const int beg = g_cnt[n], end = g_cnt[n + 1];
    for (int base = beg; base < end; base += 8) {
        int myIdx = (base + l < end) ? __ldg(g_eidx + base + l) : 0;
        int cnt = end - base; if (cnt > 8) cnt = 8;
        for (int j = 0; j < cnt; j++) {
            int pk = __shfl_sync(0xFFFFFFFFu, myIdx, j, 8);
            int s = pk & 0xFFFFF;
            int r = pk >> 20;
            float4 v = *reinterpret_cast<const float4*>(
                g_C2 + (size_t)s * NC2P + r * DOUT + l * 4);
            acc.x += v.x; acc.y += v.y; acc.z += v.z; acc.w += v.w;
        }
    }
    *reinterpret_cast<float4*>(out + (size_t)n * DOUT + l * 4) = acc;
}

// ---------------------------------------------------------------------------
// kernel_launch
// ---------------------------------------------------------------------------
extern "C" void kernel_launch(void* const* d_in, const int* in_sizes, int n_in,
                              void* d_out, int out_size)
{
    const float* feat = (const float*)d_in[0];
    const int*   src  = (const int*)  d_in[1];
    const int*   dst  = (const int*)  d_in[2];
    const int*   ety  = (const int*)  d_in[3];
    const float* W1   = (const float*)d_in[4];
    const float* Ws1  = (const float*)d_in[5];
    const float* b1   = (const float*)d_in[6];
    const float* W2   = (const float*)d_in[7];
    const float* Ws2  = (const float*)d_in[8];
    const float* b2   = (const float*)d_in[9];
    float* out = (float*)d_out;

    int Nn = in_sizes[0] / DIN;
    int Ne = in_sizes[1];
    int MT = (Nn + 63) / 64;

    float *pC1, *pC2, *pH1;
    __nv_bfloat16 *pAs, *pB1, *pB2;
    cudaGetSymbolAddress((void**)&pC1, g_C1);
    cudaGetSymbolAddress((void**)&pC2, g_C2);
    cudaGetSymbolAddress((void**)&pH1, g_h1);
    cudaGetSymbolAddress((void**)&pAs, g_As);
    cudaGetSymbolAddress((void**)&pB1, g_B1s);
    cudaGetSymbolAddress((void**)&pB2, g_B2s);

    // CSR build (independent of GEMM1; runs first on the stream).
    zero_cnt_k<<<(SCAN_N + 255) / 256, 256>>>();
    hist_k<<<(Ne + 255) / 256, 256>>>(dst, Ne);
    scan1_k<<<SCAN_NB, SCAN_B>>>();
    scan2_k<<<1, 128>>>();
    scan3_k<<<(SCAN_N + 255) / 256, 256>>>();
    scatter_k<<<(Ne + 255) / 256, 256>>>(src, dst, ety, Ne);

    pack_B_k<<<(14 * 4096 + 255) / 256, 256>>>(W1, Ws1, W2, Ws2);
    split_A_k<<<(MPAD64 * 32 + 255) / 256, 256>>>(feat, Nn, 0);

    gemm_mma<<<MT, 256, SMEM_BYTES>>>(pAs, pB1, pC1, Nn, 9, NC1);
    gather1_k<<<(Nn * 16 + 255) / 256, 256>>>(b1, Nn);

    split_A_k<<<(MPAD64 * 32 + 255) / 256, 256>>>(pH1, Nn, 1);
    gemm_mma<<<MT, 256, SMEM_BYTES>>>(pAs, pB2, pC2, Nn, 5, NC2P);
    gather2_k<<<(Nn * 8 + 255) / 256, 256>>>(b2, out, Nn);
}